// round 1
// baseline (speedup 1.0000x reference)
#include <cuda_runtime.h>

#define Bn 4
#define Cn 32
#define Hn 512
#define Wn 512
#define HWn (Hn * Wn)

__global__ __launch_bounds__(256) void warp_add_kernel(
    const float* __restrict__ x,
    const float* __restrict__ flow,
    const float* __restrict__ residual,
    float* __restrict__ out)
{
    // 32x8 spatial tile per 256-thread block; one thread per pixel, loops channels.
    const int w = blockIdx.x * 32 + (threadIdx.x & 31);
    const int h = blockIdx.y * 8  + (threadIdx.x >> 5);
    const int b = blockIdx.z;
    const int pix = h * Wn + w;

    const float* fb = flow + (size_t)b * 2 * HWn;
    const float fx = fb[pix];
    const float fy = fb[HWn + pix];

    // base grid (align_corners=False, pixel centers), plus flow
    float gx = (w + 0.5f) * (2.0f / Wn) - 1.0f + fx;
    float gy = (h + 0.5f) * (2.0f / Hn) - 1.0f + fy;

    // circular wrap on x only: mod(gx+1, 2) - 1, mod result in [0,2)
    float t = gx + 1.0f;
    t = t - floorf(t * 0.5f) * 2.0f;
    gx = t - 1.0f;

    const float rx = (gx + 1.0f) * (Wn * 0.5f) - 0.5f;
    const float ry = (gy + 1.0f) * (Hn * 0.5f) - 0.5f;

    const float x0f = floorf(rx);
    const float y0f = floorf(ry);
    const float dx = rx - x0f;
    const float dy = ry - y0f;

    const int ix0 = (int)x0f;
    const int iy0 = (int)y0f;
    const int ix1 = ix0 + 1;
    const int iy1 = iy0 + 1;

    // validity (zero-fill) folded into weights
    const float vx0 = (ix0 >= 0 && ix0 < Wn) ? 1.0f : 0.0f;
    const float vx1 = (ix1 >= 0 && ix1 < Wn) ? 1.0f : 0.0f;
    const float vy0 = (iy0 >= 0 && iy0 < Hn) ? 1.0f : 0.0f;
    const float vy1 = (iy1 >= 0 && iy1 < Hn) ? 1.0f : 0.0f;

    const float w_tl = (1.0f - dx) * (1.0f - dy) * vx0 * vy0;
    const float w_tr = dx * (1.0f - dy) * vx1 * vy0;
    const float w_bl = (1.0f - dx) * dy * vx0 * vy1;
    const float w_br = dx * dy * vx1 * vy1;

    // clipped gather offsets
    const int cx0 = min(max(ix0, 0), Wn - 1);
    const int cx1 = min(max(ix1, 0), Wn - 1);
    const int cy0 = min(max(iy0, 0), Hn - 1);
    const int cy1 = min(max(iy1, 0), Hn - 1);

    const int o_tl = cy0 * Wn + cx0;
    const int o_tr = cy0 * Wn + cx1;
    const int o_bl = cy1 * Wn + cx0;
    const int o_br = cy1 * Wn + cx1;

    const float* xb = x + (size_t)b * Cn * HWn;
    const float* rb = residual + (size_t)b * Cn * HWn + pix;
    float*       ob = out + (size_t)b * Cn * HWn + pix;

#pragma unroll 8
    for (int c = 0; c < Cn; ++c) {
        const float* xc = xb + c * HWn;
        float v = w_tl * __ldg(xc + o_tl)
                + w_tr * __ldg(xc + o_tr)
                + w_bl * __ldg(xc + o_bl)
                + w_br * __ldg(xc + o_br)
                + __ldg(rb + c * HWn);
        ob[c * HWn] = v;
    }
}

extern "C" void kernel_launch(void* const* d_in, const int* in_sizes, int n_in,
                              void* d_out, int out_size)
{
    const float* x        = (const float*)d_in[0];
    const float* flow     = (const float*)d_in[1];
    const float* residual = (const float*)d_in[2];
    float*       out      = (float*)d_out;

    dim3 grid(Wn / 32, Hn / 8, Bn);
    dim3 block(256);
    warp_add_kernel<<<grid, block>>>(x, flow, residual, out);
}

// round 2
// speedup vs baseline: 2.3048x; 2.3048x over previous
#include <cuda_runtime.h>

#define Bn 4
#define Cn 32
#define Hn 512
#define Wn 512
#define HWn (Hn * Wn)

// NHWC scratch copy of x: [B][H][W][C], 4*512*512*32 floats = 128 MB
__device__ float g_xt[(size_t)Bn * Hn * Wn * Cn];

// ---------------------------------------------------------------------------
// Pass 1: NCHW -> NHWC transpose. Block = 32 c x 32 w tile at fixed (b, h).
// ---------------------------------------------------------------------------
__global__ __launch_bounds__(256) void transpose_kernel(const float* __restrict__ x)
{
    __shared__ float tile[32][33];
    const int w0 = blockIdx.x * 32;
    const int h  = blockIdx.y;
    const int b  = blockIdx.z;
    const int wi = threadIdx.x & 31;
    const int ci = threadIdx.x >> 5;   // 0..7

    const float* xb = x + (size_t)b * Cn * HWn + h * Wn + w0;
#pragma unroll
    for (int cc = 0; cc < 32; cc += 8)
        tile[cc + ci][wi] = xb[(size_t)(cc + ci) * HWn + wi];
    __syncthreads();

    float* xtb = g_xt + (((size_t)b * Hn + h) * Wn + w0) * Cn;
#pragma unroll
    for (int ww = 0; ww < 32; ww += 8) {
        const int wj = ww + ci;
        xtb[(size_t)wj * Cn + wi] = tile[wi][wj];   // 32 channels contiguous per pixel
    }
}

// ---------------------------------------------------------------------------
// Pass 2: gather from NHWC (one pixel = one 128B line), smem-transpose,
// coalesced residual-add + NCHW store.
// Block = 32 pixels (one w-strip) x 32 channels. 8 lanes per pixel, float4/lane.
// ---------------------------------------------------------------------------
__global__ __launch_bounds__(256) void warp_gather_kernel(
    const float* __restrict__ flow,
    const float* __restrict__ residual,
    float* __restrict__ out)
{
    __shared__ float sres[32 * 33];   // [pixel][channel], padded

    const int w0  = blockIdx.x * 32;
    const int h   = blockIdx.y;
    const int b   = blockIdx.z;
    const int tid = threadIdx.x;

    // ---- gather phase: thread = (pixel i, channel-quad q) ----
    const int i = tid >> 3;     // 0..31  pixel within strip
    const int q = tid & 7;      // 0..7   channel quad (4 channels)
    const int w = w0 + i;
    const int pix = h * Wn + w;

    const float* fb = flow + (size_t)b * 2 * HWn;
    const float fx = __ldg(fb + pix);
    const float fy = __ldg(fb + HWn + pix);

    float gx = (w + 0.5f) * (2.0f / Wn) - 1.0f + fx;
    float gy = (h + 0.5f) * (2.0f / Hn) - 1.0f + fy;

    // circular wrap on x: mod(gx+1, 2) - 1
    float t = gx + 1.0f;
    t = t - floorf(t * 0.5f) * 2.0f;
    gx = t - 1.0f;

    const float rx = (gx + 1.0f) * (Wn * 0.5f) - 0.5f;
    const float ry = (gy + 1.0f) * (Hn * 0.5f) - 0.5f;

    const float x0f = floorf(rx);
    const float y0f = floorf(ry);
    const float dx = rx - x0f;
    const float dy = ry - y0f;

    const int ix0 = (int)x0f, iy0 = (int)y0f;
    const int ix1 = ix0 + 1,  iy1 = iy0 + 1;

    const float vx0 = (ix0 >= 0 && ix0 < Wn) ? 1.0f : 0.0f;
    const float vx1 = (ix1 >= 0 && ix1 < Wn) ? 1.0f : 0.0f;
    const float vy0 = (iy0 >= 0 && iy0 < Hn) ? 1.0f : 0.0f;
    const float vy1 = (iy1 >= 0 && iy1 < Hn) ? 1.0f : 0.0f;

    const float w_tl = (1.0f - dx) * (1.0f - dy) * vx0 * vy0;
    const float w_tr = dx * (1.0f - dy) * vx1 * vy0;
    const float w_bl = (1.0f - dx) * dy * vx0 * vy1;
    const float w_br = dx * dy * vx1 * vy1;

    const int cx0 = min(max(ix0, 0), Wn - 1);
    const int cx1 = min(max(ix1, 0), Wn - 1);
    const int cy0 = min(max(iy0, 0), Hn - 1);
    const int cy1 = min(max(iy1, 0), Hn - 1);

    const float* xb = g_xt + (size_t)b * HWn * Cn + q * 4;
    const float4 tl = __ldg((const float4*)(xb + (size_t)(cy0 * Wn + cx0) * Cn));
    const float4 tr = __ldg((const float4*)(xb + (size_t)(cy0 * Wn + cx1) * Cn));
    const float4 bl = __ldg((const float4*)(xb + (size_t)(cy1 * Wn + cx0) * Cn));
    const float4 br = __ldg((const float4*)(xb + (size_t)(cy1 * Wn + cx1) * Cn));

    float4 r;
    r.x = w_tl * tl.x + w_tr * tr.x + w_bl * bl.x + w_br * br.x;
    r.y = w_tl * tl.y + w_tr * tr.y + w_bl * bl.y + w_br * br.y;
    r.z = w_tl * tl.z + w_tr * tr.z + w_bl * bl.z + w_br * br.z;
    r.w = w_tl * tl.w + w_tr * tr.w + w_bl * bl.w + w_br * br.w;

    float* s = sres + i * 33 + q * 4;
    s[0] = r.x; s[1] = r.y; s[2] = r.z; s[3] = r.w;
    __syncthreads();

    // ---- write phase: thread = (w lane, channel group), fully coalesced ----
    const int wi = tid & 31;
    const int cg = tid >> 5;   // 0..7
    const size_t base = (size_t)b * Cn * HWn + h * Wn + w0 + wi;
#pragma unroll
    for (int cc = 0; cc < 32; cc += 8) {
        const int c = cc + cg;
        const size_t o = base + (size_t)c * HWn;
        out[o] = sres[wi * 33 + c] + __ldg(residual + o);
    }
}

extern "C" void kernel_launch(void* const* d_in, const int* in_sizes, int n_in,
                              void* d_out, int out_size)
{
    const float* x        = (const float*)d_in[0];
    const float* flow     = (const float*)d_in[1];
    const float* residual = (const float*)d_in[2];
    float*       out      = (float*)d_out;

    dim3 grid(Wn / 32, Hn, Bn);
    transpose_kernel<<<grid, 256>>>(x);
    warp_gather_kernel<<<grid, 256>>>(flow, residual, out);
}

// round 3
// speedup vs baseline: 2.9462x; 1.2783x over previous
#include <cuda_runtime.h>
#include <cuda_fp16.h>

#define Bn 4
#define Cn 32
#define Hn 512
#define Wn 512
#define HWn (Hn * Wn)
#define PSTRIP 64

// NHWC fp16 scratch copy of x: [B][H][W][C] = 64 MB
__device__ __half g_xt[(size_t)Bn * Hn * Wn * Cn];

// ---------------------------------------------------------------------------
// Pass 1: NCHW fp32 -> NHWC fp16.  Block = (32 c) x (32 w) tile at fixed (b,h).
// Loads: float4 across w (fully coalesced). Stores: uint2 (4 halves) per
// thread, consecutive within pixel -> coalesced 64B pixels.
// ---------------------------------------------------------------------------
__global__ __launch_bounds__(256) void transpose_kernel(const float* __restrict__ x)
{
    __shared__ float tile[32][33];
    const int w0 = blockIdx.x * 32;
    const int h  = blockIdx.y;
    const int b  = blockIdx.z;
    const int tid = threadIdx.x;

    // load: thread (c = tid>>3, wq = tid&7) reads float4 at w0 + wq*4
    const int c  = tid >> 3;
    const int wq = tid & 7;
    const float4 v = __ldg((const float4*)(
        x + ((size_t)b * Cn + c) * HWn + h * Wn + w0 + wq * 4));
    tile[wq * 4 + 0][c] = v.x;
    tile[wq * 4 + 1][c] = v.y;
    tile[wq * 4 + 2][c] = v.z;
    tile[wq * 4 + 3][c] = v.w;
    __syncthreads();

    // store: thread (pix = tid>>3, part = tid&7) writes channels part*4..+3
    const int pix  = tid >> 3;
    const int part = tid & 7;
    const __half2 h0 = __floats2half2_rn(tile[pix][part * 4 + 0],
                                         tile[pix][part * 4 + 1]);
    const __half2 h1 = __floats2half2_rn(tile[pix][part * 4 + 2],
                                         tile[pix][part * 4 + 3]);
    uint2 u;
    u.x = *(const unsigned int*)&h0;
    u.y = *(const unsigned int*)&h1;
    *(uint2*)((char*)(g_xt + (((size_t)b * Hn + h) * Wn + w0 + pix) * Cn)
              + part * 8) = u;
}

// ---------------------------------------------------------------------------
// Pass 2: per-pixel params once (smem broadcast), fp16 NHWC gathers with
// 4 lanes x 16B per pixel, smem transpose, coalesced residual-add + NCHW store.
// Block = 64-pixel w-strip at fixed (b,h).
// ---------------------------------------------------------------------------
__global__ __launch_bounds__(256) void warp_gather_kernel(
    const float* __restrict__ flow,
    const float* __restrict__ residual,
    float* __restrict__ out)
{
    __shared__ float s_wt[4][PSTRIP];   // tl,tr,bl,br weights
    __shared__ int   s_of[4][PSTRIP];   // tl,tr,bl,br pixel offsets
    __shared__ float sres[PSTRIP * 33]; // [pixel][channel]

    const int w0  = blockIdx.x * PSTRIP;
    const int h   = blockIdx.y;
    const int b   = blockIdx.z;
    const int tid = threadIdx.x;

    // ---- phase 0: 64 threads compute per-pixel sampling params ----
    if (tid < PSTRIP) {
        const int w = w0 + tid;
        const int pix = h * Wn + w;
        const float* fb = flow + (size_t)b * 2 * HWn;
        const float fx = __ldg(fb + pix);
        const float fy = __ldg(fb + HWn + pix);

        float gx = (w + 0.5f) * (2.0f / Wn) - 1.0f + fx;
        float gy = (h + 0.5f) * (2.0f / Hn) - 1.0f + fy;

        // circular wrap on x: mod(gx+1, 2) - 1
        float t = gx + 1.0f;
        t = t - floorf(t * 0.5f) * 2.0f;
        gx = t - 1.0f;

        const float rx = (gx + 1.0f) * (Wn * 0.5f) - 0.5f;
        const float ry = (gy + 1.0f) * (Hn * 0.5f) - 0.5f;

        const float x0f = floorf(rx);
        const float y0f = floorf(ry);
        const float dx = rx - x0f;
        const float dy = ry - y0f;

        const int ix0 = (int)x0f, iy0 = (int)y0f;
        const int ix1 = ix0 + 1,  iy1 = iy0 + 1;

        const float vx0 = (ix0 >= 0 && ix0 < Wn) ? 1.0f : 0.0f;
        const float vx1 = (ix1 >= 0 && ix1 < Wn) ? 1.0f : 0.0f;
        const float vy0 = (iy0 >= 0 && iy0 < Hn) ? 1.0f : 0.0f;
        const float vy1 = (iy1 >= 0 && iy1 < Hn) ? 1.0f : 0.0f;

        s_wt[0][tid] = (1.0f - dx) * (1.0f - dy) * vx0 * vy0;
        s_wt[1][tid] = dx * (1.0f - dy) * vx1 * vy0;
        s_wt[2][tid] = (1.0f - dx) * dy * vx0 * vy1;
        s_wt[3][tid] = dx * dy * vx1 * vy1;

        const int cx0 = min(max(ix0, 0), Wn - 1);
        const int cx1 = min(max(ix1, 0), Wn - 1);
        const int cy0 = min(max(iy0, 0), Hn - 1);
        const int cy1 = min(max(iy1, 0), Hn - 1);
        s_of[0][tid] = cy0 * Wn + cx0;
        s_of[1][tid] = cy0 * Wn + cx1;
        s_of[2][tid] = cy1 * Wn + cx0;
        s_of[3][tid] = cy1 * Wn + cx1;
    }
    __syncthreads();

    // ---- phase 1: gather. thread = (pixel i, 8-channel group q) ----
    {
        const int i = tid >> 2;     // 0..63
        const int q = tid & 3;      // 0..3 (channels q*8 .. q*8+7)
        const float w_tl = s_wt[0][i], w_tr = s_wt[1][i];
        const float w_bl = s_wt[2][i], w_br = s_wt[3][i];
        const __half* xb = g_xt + (size_t)b * HWn * Cn + q * 8;

        float r[8];
#pragma unroll
        for (int k = 0; k < 8; ++k) r[k] = 0.0f;

#pragma unroll
        for (int cnr = 0; cnr < 4; ++cnr) {
            const float wt = s_wt[cnr][i];
            const uint4 ld = __ldg((const uint4*)(xb + (size_t)s_of[cnr][i] * Cn));
            const unsigned int uu[4] = {ld.x, ld.y, ld.z, ld.w};
#pragma unroll
            for (int j = 0; j < 4; ++j) {
                const float2 f = __half22float2(*(const __half2*)&uu[j]);
                r[j * 2 + 0] += wt * f.x;
                r[j * 2 + 1] += wt * f.y;
            }
        }

        float* s = sres + i * 33 + q * 8;
#pragma unroll
        for (int k = 0; k < 8; ++k) s[k] = r[k];
    }
    __syncthreads();

    // ---- phase 2: coalesced residual-add + NCHW store ----
    {
        const int wi = tid & 63;    // 0..63
        const int cg = tid >> 6;    // 0..3
        const size_t base = (size_t)b * Cn * HWn + h * Wn + w0 + wi;
#pragma unroll
        for (int cc = 0; cc < 32; cc += 4) {
            const int c = cc + cg;
            const size_t o = base + (size_t)c * HWn;
            out[o] = sres[wi * 33 + c] + __ldg(residual + o);
        }
    }
}

extern "C" void kernel_launch(void* const* d_in, const int* in_sizes, int n_in,
                              void* d_out, int out_size)
{
    const float* x        = (const float*)d_in[0];
    const float* flow     = (const float*)d_in[1];
    const float* residual = (const float*)d_in[2];
    float*       out      = (float*)d_out;

    dim3 gridT(Wn / 32, Hn, Bn);
    transpose_kernel<<<gridT, 256>>>(x);
    dim3 gridG(Wn / PSTRIP, Hn, Bn);
    warp_gather_kernel<<<gridG, 256>>>(flow, residual, out);
}